// round 14
// baseline (speedup 1.0000x reference)
#include <cuda_runtime.h>
#include <cuda_fp16.h>
#include <mma.h>
#include <cstdint>

using namespace nvcuda;

#define N_NODES 50000
#define N_PAD   50048   // 391 * 128 : full-tile padding for GEMM
#define N_EDGES 1000000
#define H_DIM   128
#define OUT_DIM 64
#define N_RELS  16

// ---------------- scratch (device globals; no runtime allocation) ----------------
__device__ __align__(256) __half g_Xh [N_PAD * H_DIM];               // fp16 x (pad rows BSS-zero)
__device__ __align__(256) __half g_W1h[N_RELS * H_DIM * H_DIM];      // fp16 W1
__device__ __align__(256) __half g_W2h[N_RELS * H_DIM * OUT_DIM];    // fp16 W2
__device__ __align__(256) __half g_Y1h[(size_t)N_RELS * N_PAD * H_DIM];   // ~205 MB
__device__ __align__(256) __half g_Y2h[(size_t)N_RELS * N_PAD * OUT_DIM]; // ~102 MB
__device__ __align__(256) float  g_h1 [N_PAD * H_DIM];               // fp32 atomic target
__device__ __align__(256) __half g_h1h[N_PAD * H_DIM];               // fp16 copy for GEMM2
__device__ __align__(256) int4   g_edges[N_EDGES];                   // packed {etype,src,dst,norm}

// ---------------- helpers ----------------
__device__ __forceinline__ uint32_t smem_u32(const void* p) {
    uint32_t a;
    asm("{ .reg .u64 t; cvta.to.shared.u64 t, %1; cvt.u32.u64 %0, t; }" : "=r"(a) : "l"(p));
    return a;
}
__device__ __forceinline__ void cp_async16(uint32_t s, const void* g) {
    asm volatile("cp.async.cg.shared.global [%0], [%1], 16;" :: "r"(s), "l"(g));
}
#define CP_COMMIT() asm volatile("cp.async.commit_group;" ::: "memory")
#define CP_WAIT0()  asm volatile("cp.async.wait_group 0;" ::: "memory")

// ---------------- gather + zero + edge-pack (fused prep) ----------------
// idx space A: [0, N*16)             gather X -> fp16
// idx space B: [N*16, N*48)          zero g_h1 (float4)
// idx space C: [N*48, N*64)          zero out  (float4)
// idx space D: [N*64, N*64+E)        pack edge records
__global__ void prep_kernel(const int* __restrict__ ids,
                            const float* __restrict__ emb,
                            float* __restrict__ out_ext,
                            const int* __restrict__ etype,
                            const int* __restrict__ src,
                            const int* __restrict__ dst,
                            const float* __restrict__ norm) {
    int i = blockIdx.x * blockDim.x + threadIdx.x;
    if (i < N_NODES * 16) {
        int node = i >> 4;
        int c8   = i & 15;
        const float4* e4 = (const float4*)(emb + (size_t)ids[node] * H_DIM);
        float4 f0 = e4[c8 * 2], f1 = e4[c8 * 2 + 1];
        __half2 h[4];
        h[0] = __floats2half2_rn(f0.x, f0.y);
        h[1] = __floats2half2_rn(f0.z, f0.w);
        h[2] = __floats2half2_rn(f1.x, f1.y);
        h[3] = __floats2half2_rn(f1.z, f1.w);
        ((uint4*)g_Xh)[(size_t)node * 16 + c8] = *(uint4*)h;
        return;
    }
    int j = i - N_NODES * 16;
    if (j >= 0 && j < N_NODES * 32) {
        ((float4*)g_h1)[j] = make_float4(0.f, 0.f, 0.f, 0.f);
        return;
    }
    int k = i - N_NODES * 48;
    if (k >= 0 && k < N_NODES * 16) {
        ((float4*)out_ext)[k] = make_float4(0.f, 0.f, 0.f, 0.f);
        return;
    }
    int e = i - N_NODES * 64;
    if (e >= 0 && e < N_EDGES)
        g_edges[e] = make_int4(etype[e], src[e], dst[e],
                               __float_as_int(norm[e]));
}

template <int OUTW>
__global__ void compute_W_kernel(const float* __restrict__ comp,
                                 const float* __restrict__ V) {
    const int sz = H_DIM * OUTW;
    int j = blockIdx.x * blockDim.x + threadIdx.x;
    int r = blockIdx.y;
    if (j < sz) {
        float acc = 0.f;
        #pragma unroll
        for (int b = 0; b < N_RELS; b++)
            acc += comp[r * N_RELS + b] * V[(size_t)b * sz + j];
        __half* Wh = (OUTW == H_DIM) ? g_W1h : g_W2h;
        Wh[(size_t)r * sz + j] = __float2half(acc);
    }
}

// ---------------- wmma fp16 GEMM, rel-loop + cp.async double-buffered W ----------
// Handles rels [rel_base, rel_base+4). Grid (391, 1).
template <int LAYER>
__global__ __launch_bounds__(256, 2) void gemm_wmma_kernel(int rel_base) {
    constexpr int BN  = (LAYER == 1) ? 128 : 64;
    constexpr int AP  = 136;            // A smem pitch (halves)
    constexpr int BP  = BN + 8;         // W smem pitch (halves)
    constexpr int NF  = BN / 2 / 16;    // n-frags per warp (4 | 2)
    constexpr int NU8 = BN / 8;         // 8-half chunks per W row
    constexpr int RG  = 4;              // relations per CTA

    extern __shared__ __half sm[];
    __half* a_s = sm;
    __half* w_s[2] = { a_s + 128 * AP, a_s + 128 * AP + 128 * BP };

    const int tid  = threadIdx.x;
    const int m0   = blockIdx.x * 128;
    const int rel0 = rel_base;

    const __half* __restrict__ Ap = (LAYER == 1) ? g_Xh : g_h1h;
    const __half* __restrict__ Wbase = (LAYER == 1) ? g_W1h : g_W2h;
    __half* __restrict__ Ybase = (LAYER == 1) ? g_Y1h : g_Y2h;

    const uint32_t a_u32  = smem_u32(a_s);
    const uint32_t w_u32[2] = { smem_u32(w_s[0]), smem_u32(w_s[1]) };

    // ---- prologue: cp.async A tile + W tile for rel0 ----
    #pragma unroll
    for (int i = tid; i < 128 * 16; i += 256) {
        int row = i >> 4, c8 = i & 15;
        cp_async16(a_u32 + (row * AP + c8 * 8) * 2,
                   Ap + (size_t)(m0 + row) * H_DIM + c8 * 8);
    }
    {
        const __half* W0 = Wbase + (size_t)rel0 * H_DIM * BN;
        #pragma unroll
        for (int i = tid; i < 128 * NU8; i += 256) {
            int row = i / NU8, c8 = (i % NU8) * 8;
            cp_async16(w_u32[0] + (row * BP + c8) * 2, W0 + (size_t)row * BN + c8);
        }
    }
    CP_COMMIT();

    const int wid = tid >> 5;
    const int wm  = wid & 3;      // m offset wm*32
    const int wn  = wid >> 2;     // n offset wn*(BN/2)

    #pragma unroll
    for (int g = 0; g < RG; g++) {
        CP_WAIT0();
        __syncthreads();

        if (g + 1 < RG) {
            const __half* Wn = Wbase + (size_t)(rel0 + g + 1) * H_DIM * BN;
            #pragma unroll
            for (int i = tid; i < 128 * NU8; i += 256) {
                int row = i / NU8, c8 = (i % NU8) * 8;
                cp_async16(w_u32[(g + 1) & 1] + (row * BP + c8) * 2,
                           Wn + (size_t)row * BN + c8);
            }
            CP_COMMIT();
        }

        __half* b_s = w_s[g & 1];

        wmma::fragment<wmma::accumulator, 16, 16, 16, float> acc[2][NF];
        #pragma unroll
        for (int i = 0; i < 2; i++)
            #pragma unroll
            for (int j = 0; j < NF; j++)
                wmma::fill_fragment(acc[i][j], 0.f);

        #pragma unroll
        for (int k0 = 0; k0 < 128; k0 += 16) {
            wmma::fragment<wmma::matrix_a, 16, 16, 16, __half, wmma::row_major> af[2];
            #pragma unroll
            for (int i = 0; i < 2; i++)
                wmma::load_matrix_sync(af[i], a_s + (wm * 32 + i * 16) * AP + k0, AP);
            #pragma unroll
            for (int j = 0; j < NF; j++) {
                wmma::fragment<wmma::matrix_b, 16, 16, 16, __half, wmma::row_major> bf;
                wmma::load_matrix_sync(bf, b_s + k0 * BP + wn * (BN / 2) + j * 16, BP);
                #pragma unroll
                for (int i = 0; i < 2; i++)
                    wmma::mma_sync(acc[i][j], af[i], bf, acc[i][j]);
            }
        }

        __half* Yp = Ybase + (size_t)(rel0 + g) * N_PAD * BN;
        #pragma unroll
        for (int i = 0; i < 2; i++)
            #pragma unroll
            for (int j = 0; j < NF; j++) {
                wmma::fragment<wmma::accumulator, 16, 16, 16, __half> hacc;
                #pragma unroll
                for (int e = 0; e < hacc.num_elements; e++)
                    hacc.x[e] = __float2half(acc[i][j].x[e]);
                wmma::store_matrix_sync(
                    Yp + (size_t)(m0 + wm * 32 + i * 16) * BN + wn * (BN / 2) + j * 16,
                    hacc, BN, wmma::mem_row_major);
            }
    }
}

// ---------------- edge scatter (group-predicated) ----------------
__device__ __forceinline__ void red_add_v4(float* p, float4 v) {
    asm volatile("red.global.add.v4.f32 [%0], {%1, %2, %3, %4};"
                 :: "l"(p), "f"(v.x), "f"(v.y), "f"(v.z), "f"(v.w) : "memory");
}

// layer 1: one warp per edge; only edges with etype>>2 == grp
__global__ void scatter1_kernel(int grp) {
    int e = (blockIdx.x * blockDim.x + threadIdx.x) >> 5;
    if (e >= N_EDGES) return;
    int4 rec = __ldg(g_edges + e);
    if ((rec.x >> 2) != grp) return;

    int   lane = threadIdx.x & 31;
    float nm   = __int_as_float(rec.w);

    uint2 v = __ldg((const uint2*)(g_Y1h + ((size_t)rec.x * N_PAD + rec.y) * H_DIM) + lane);
    float2 f0 = __half22float2(*(__half2*)&v.x);
    float2 f1 = __half22float2(*(__half2*)&v.y);
    red_add_v4(g_h1 + (size_t)rec.z * H_DIM + lane * 4,
               make_float4(f0.x * nm, f0.y * nm, f1.x * nm, f1.y * nm));
}

// layer 2: two edges per warp (16 lanes each); only edges with etype>>2 == grp
__global__ void scatter2_kernel(int grp, float* __restrict__ out_ext) {
    int t = blockIdx.x * blockDim.x + threadIdx.x;
    int e = t >> 4;
    if (e >= N_EDGES) return;
    int4 rec = __ldg(g_edges + e);
    if ((rec.x >> 2) != grp) return;

    int   lane = t & 15;
    float nm   = __int_as_float(rec.w);

    uint2 v = __ldg((const uint2*)(g_Y2h + ((size_t)rec.x * N_PAD + rec.y) * OUT_DIM) + lane);
    float2 f0 = __half22float2(*(__half2*)&v.x);
    float2 f1 = __half22float2(*(__half2*)&v.y);
    red_add_v4(out_ext + (size_t)rec.z * OUT_DIM + lane * 4,
               make_float4(f0.x * nm, f0.y * nm, f1.x * nm, f1.y * nm));
}

// ---------------- epilogues ----------------
__global__ void bias_relu_kernel(const float* __restrict__ bias1) {
    int i = blockIdx.x * blockDim.x + threadIdx.x;  // over N_NODES*32 float4
    if (i < N_NODES * 32) {
        int c4 = i & 31;
        float4 v = ((float4*)g_h1)[i];
        const float4 b = ((const float4*)bias1)[c4];
        v.x = fmaxf(v.x + b.x, 0.f);
        v.y = fmaxf(v.y + b.y, 0.f);
        v.z = fmaxf(v.z + b.z, 0.f);
        v.w = fmaxf(v.w + b.w, 0.f);
        ((float4*)g_h1)[i] = v;
        __half2 h0 = __floats2half2_rn(v.x, v.y);
        __half2 h1v = __floats2half2_rn(v.z, v.w);
        ((uint2*)g_h1h)[i] = make_uint2(*(uint32_t*)&h0, *(uint32_t*)&h1v);
    }
}

__global__ void bias2_kernel(const float* __restrict__ bias2,
                             float* __restrict__ out_ext) {
    int i = blockIdx.x * blockDim.x + threadIdx.x;
    if (i < N_NODES * 16) {
        int c4 = i & 15;
        float4 v = ((float4*)out_ext)[i];
        const float4 b = ((const float4*)bias2)[c4];
        v.x += b.x; v.y += b.y; v.z += b.z; v.w += b.w;
        ((float4*)out_ext)[i] = v;
    }
}

// ---------------- launch ----------------
extern "C" void kernel_launch(void* const* d_in, const int* in_sizes, int n_in,
                              void* d_out, int out_size) {
    const int*   node_ids = (const int*)  d_in[0];
    const int*   src      = (const int*)  d_in[1];
    const int*   dst      = (const int*)  d_in[2];
    const int*   etype    = (const int*)  d_in[3];
    const float* norm     = (const float*)d_in[4];
    const float* emb      = (const float*)d_in[5];
    const float* V1       = (const float*)d_in[6];
    const float* comp1    = (const float*)d_in[7];
    const float* bias1    = (const float*)d_in[8];
    const float* V2       = (const float*)d_in[9];
    const float* comp2    = (const float*)d_in[10];
    const float* bias2    = (const float*)d_in[11];
    float*       out      = (float*)d_out;

    const int T = 256;
    const int SMEM1 = (128 * 136 + 2 * 128 * (128 + 8)) * 2;
    const int SMEM2 = (128 * 136 + 2 * 128 * (64 + 8)) * 2;
    cudaFuncSetAttribute(gemm_wmma_kernel<1>, cudaFuncAttributeMaxDynamicSharedMemorySize, SMEM1);
    cudaFuncSetAttribute(gemm_wmma_kernel<2>, cudaFuncAttributeMaxDynamicSharedMemorySize, SMEM2);

    // Side stream + events (forked from the capturing stream via events; joined
    // back before dependent work). Created fresh per call — kernel_launch is
    // invoked only a handful of times, and creation allocates no device memory.
    cudaStream_t side;
    cudaStreamCreateWithFlags(&side, cudaStreamNonBlocking);
    cudaEvent_t ev[8], evj[2];
    for (int i = 0; i < 8; i++) cudaEventCreateWithFlags(&ev[i], cudaEventDisableTiming);
    for (int i = 0; i < 2; i++) cudaEventCreateWithFlags(&evj[i], cudaEventDisableTiming);

    // prep: gather X (fp16) + zero h1/out + pack edges
    {
        long long n = (long long)N_NODES * 64 + N_EDGES;
        prep_kernel<<<(unsigned)((n + T - 1) / T), T>>>(node_ids, emb, out,
                                                        etype, src, dst, norm);
    }
    // combine basis weights -> fp16
    {
        dim3 g1((H_DIM * H_DIM + T - 1) / T, N_RELS);
        compute_W_kernel<H_DIM><<<g1, T>>>(comp1, V1);
        dim3 g2((H_DIM * OUT_DIM + T - 1) / T, N_RELS);
        compute_W_kernel<OUT_DIM><<<g2, T>>>(comp2, V2);
    }

    const unsigned SC1_GRID = (unsigned)(((long long)N_EDGES * 32 + 511) / 512);
    const unsigned SC2_GRID = (unsigned)(((long long)N_EDGES * 16 + 511) / 512);

    // ---- layer 1: GEMM groups on main stream, scatter groups overlapped on side ----
    for (int g = 0; g < 4; g++) {
        gemm_wmma_kernel<1><<<dim3(N_PAD / 128, 1), 256, SMEM1>>>(g * 4);
        cudaEventRecord(ev[g], 0);
        cudaStreamWaitEvent(side, ev[g], 0);
        scatter1_kernel<<<SC1_GRID, 512, 0, side>>>(g);
    }
    cudaEventRecord(evj[0], side);
    cudaStreamWaitEvent(0, evj[0], 0);
    bias_relu_kernel<<<(N_NODES * 32 + T - 1) / T, T>>>(bias1);

    // ---- layer 2 ----
    for (int g = 0; g < 4; g++) {
        gemm_wmma_kernel<2><<<dim3(N_PAD / 128, 1), 256, SMEM2>>>(g * 4);
        cudaEventRecord(ev[4 + g], 0);
        cudaStreamWaitEvent(side, ev[4 + g], 0);
        scatter2_kernel<<<SC2_GRID, 512, 0, side>>>(g, out);
    }
    cudaEventRecord(evj[1], side);
    cudaStreamWaitEvent(0, evj[1], 0);
    bias2_kernel<<<(N_NODES * 16 + T - 1) / T, T>>>(bias2, out);
}

// round 16
// speedup vs baseline: 1.9427x; 1.9427x over previous
#include <cuda_runtime.h>
#include <cuda_fp16.h>
#include <mma.h>
#include <cstdint>

using namespace nvcuda;

#define N_NODES 50000
#define N_PAD   50048   // 391 * 128 : full-tile padding for GEMM
#define N_EDGES 1000000
#define H_DIM   128
#define OUT_DIM 64
#define N_RELS  16

// ---------------- scratch (device globals; no runtime allocation) ----------------
__device__ __align__(256) __half g_Xh [N_PAD * H_DIM];               // fp16 x (pad rows BSS-zero)
__device__ __align__(256) __half g_W1h[N_RELS * H_DIM * H_DIM];      // fp16 W1
__device__ __align__(256) __half g_W2h[N_RELS * H_DIM * OUT_DIM];    // fp16 W2
__device__ __align__(256) __half g_Y1h[(size_t)N_RELS * N_PAD * H_DIM];   // ~205 MB
__device__ __align__(256) __half g_Y2h[(size_t)N_RELS * N_PAD * OUT_DIM]; // ~102 MB
__device__ __align__(256) float  g_h1 [N_PAD * H_DIM];               // fp32 atomic target
__device__ __align__(256) __half g_h1h[N_PAD * H_DIM];               // fp16 copy for GEMM2
__device__ __align__(256) int4   g_edges[N_EDGES];                   // packed {etype,src,dst,norm}

// ---------------- helpers ----------------
__device__ __forceinline__ uint32_t smem_u32(const void* p) {
    uint32_t a;
    asm("{ .reg .u64 t; cvta.to.shared.u64 t, %1; cvt.u32.u64 %0, t; }" : "=r"(a) : "l"(p));
    return a;
}
__device__ __forceinline__ void cp_async16(uint32_t s, const void* g) {
    asm volatile("cp.async.cg.shared.global [%0], [%1], 16;" :: "r"(s), "l"(g));
}
#define CP_COMMIT() asm volatile("cp.async.commit_group;" ::: "memory")
#define CP_WAIT0()  asm volatile("cp.async.wait_group 0;" ::: "memory")

// ---------------- gather + zero + edge-pack (fused prep) ----------------
__global__ void prep_kernel(const int* __restrict__ ids,
                            const float* __restrict__ emb,
                            float* __restrict__ out_ext,
                            const int* __restrict__ etype,
                            const int* __restrict__ src,
                            const int* __restrict__ dst,
                            const float* __restrict__ norm) {
    int i = blockIdx.x * blockDim.x + threadIdx.x;
    if (i < N_NODES * 16) {
        int node = i >> 4;
        int c8   = i & 15;
        const float4* e4 = (const float4*)(emb + (size_t)ids[node] * H_DIM);
        float4 f0 = e4[c8 * 2], f1 = e4[c8 * 2 + 1];
        __half2 h[4];
        h[0] = __floats2half2_rn(f0.x, f0.y);
        h[1] = __floats2half2_rn(f0.z, f0.w);
        h[2] = __floats2half2_rn(f1.x, f1.y);
        h[3] = __floats2half2_rn(f1.z, f1.w);
        ((uint4*)g_Xh)[(size_t)node * 16 + c8] = *(uint4*)h;
        return;
    }
    int j = i - N_NODES * 16;
    if (j >= 0 && j < N_NODES * 32) {
        ((float4*)g_h1)[j] = make_float4(0.f, 0.f, 0.f, 0.f);
        return;
    }
    int k = i - N_NODES * 48;
    if (k >= 0 && k < N_NODES * 16) {
        ((float4*)out_ext)[k] = make_float4(0.f, 0.f, 0.f, 0.f);
        return;
    }
    int e = i - N_NODES * 64;
    if (e >= 0 && e < N_EDGES)
        g_edges[e] = make_int4(etype[e], src[e], dst[e], __float_as_int(norm[e]));
}

template <int OUTW>
__global__ void compute_W_kernel(const float* __restrict__ comp,
                                 const float* __restrict__ V) {
    const int sz = H_DIM * OUTW;
    int j = blockIdx.x * blockDim.x + threadIdx.x;
    int r = blockIdx.y;
    if (j < sz) {
        float acc = 0.f;
        #pragma unroll
        for (int b = 0; b < N_RELS; b++)
            acc += comp[r * N_RELS + b] * V[(size_t)b * sz + j];
        __half* Wh = (OUTW == H_DIM) ? g_W1h : g_W2h;
        Wh[(size_t)r * sz + j] = __float2half(acc);
    }
}

// ---------------- layer-1 GEMM: rel-loop + cp.async double-buffered W ----------
// Grid (391, 4): CTA owns one m-tile x 4 relations. (round-12 proven config)
__global__ __launch_bounds__(256, 2) void gemm1_wmma_kernel() {
    constexpr int BN  = 128;
    constexpr int AP  = 136;
    constexpr int BP  = BN + 8;
    constexpr int NF  = 4;
    constexpr int NU8 = BN / 8;
    constexpr int RG  = 4;

    extern __shared__ __half sm[];
    __half* a_s = sm;
    __half* w_s[2] = { a_s + 128 * AP, a_s + 128 * AP + 128 * BP };

    const int tid  = threadIdx.x;
    const int m0   = blockIdx.x * 128;
    const int rel0 = blockIdx.y * RG;

    const uint32_t a_u32  = smem_u32(a_s);
    const uint32_t w_u32[2] = { smem_u32(w_s[0]), smem_u32(w_s[1]) };

    #pragma unroll
    for (int i = tid; i < 128 * 16; i += 256) {
        int row = i >> 4, c8 = i & 15;
        cp_async16(a_u32 + (row * AP + c8 * 8) * 2,
                   g_Xh + (size_t)(m0 + row) * H_DIM + c8 * 8);
    }
    {
        const __half* W0 = g_W1h + (size_t)rel0 * H_DIM * BN;
        #pragma unroll
        for (int i = tid; i < 128 * NU8; i += 256) {
            int row = i / NU8, c8 = (i % NU8) * 8;
            cp_async16(w_u32[0] + (row * BP + c8) * 2, W0 + (size_t)row * BN + c8);
        }
    }
    CP_COMMIT();

    const int wid = tid >> 5;
    const int wm  = wid & 3;
    const int wn  = wid >> 2;

    #pragma unroll
    for (int g = 0; g < RG; g++) {
        CP_WAIT0();
        __syncthreads();

        if (g + 1 < RG) {
            const __half* Wn = g_W1h + (size_t)(rel0 + g + 1) * H_DIM * BN;
            #pragma unroll
            for (int i = tid; i < 128 * NU8; i += 256) {
                int row = i / NU8, c8 = (i % NU8) * 8;
                cp_async16(w_u32[(g + 1) & 1] + (row * BP + c8) * 2,
                           Wn + (size_t)row * BN + c8);
            }
            CP_COMMIT();
        }

        __half* b_s = w_s[g & 1];

        wmma::fragment<wmma::accumulator, 16, 16, 16, float> acc[2][NF];
        #pragma unroll
        for (int i = 0; i < 2; i++)
            #pragma unroll
            for (int j = 0; j < NF; j++)
                wmma::fill_fragment(acc[i][j], 0.f);

        #pragma unroll
        for (int k0 = 0; k0 < 128; k0 += 16) {
            wmma::fragment<wmma::matrix_a, 16, 16, 16, __half, wmma::row_major> af[2];
            #pragma unroll
            for (int i = 0; i < 2; i++)
                wmma::load_matrix_sync(af[i], a_s + (wm * 32 + i * 16) * AP + k0, AP);
            #pragma unroll
            for (int j = 0; j < NF; j++) {
                wmma::fragment<wmma::matrix_b, 16, 16, 16, __half, wmma::row_major> bf;
                wmma::load_matrix_sync(bf, b_s + k0 * BP + wn * 64 + j * 16, BP);
                #pragma unroll
                for (int i = 0; i < 2; i++)
                    wmma::mma_sync(acc[i][j], af[i], bf, acc[i][j]);
            }
        }

        __half* Yp = g_Y1h + (size_t)(rel0 + g) * N_PAD * BN;
        #pragma unroll
        for (int i = 0; i < 2; i++)
            #pragma unroll
            for (int j = 0; j < NF; j++) {
                wmma::fragment<wmma::accumulator, 16, 16, 16, __half> hacc;
                #pragma unroll
                for (int e = 0; e < hacc.num_elements; e++)
                    hacc.x[e] = __float2half(acc[i][j].x[e]);
                wmma::store_matrix_sync(
                    Yp + (size_t)(m0 + wm * 32 + i * 16) * BN + wn * 64 + j * 16,
                    hacc, BN, wmma::mem_row_major);
            }
    }
}

// ---------------- layer-2 GEMM: TWO rels per B tile (BN=128 = 2 x 64) ----------
// Grid (391, 4): CTA owns one m-tile x 4 relations = 2 pairs.
// Warp wn selects which rel of the pair it computes/stores.
__global__ __launch_bounds__(256, 2) void gemm2_wmma_kernel() {
    constexpr int AP  = 136;
    constexpr int BP  = 136;            // 128 cols (2 rels x 64) + pad
    constexpr int NF  = 4;

    extern __shared__ __half sm[];
    __half* a_s = sm;
    __half* w_s[2] = { a_s + 128 * AP, a_s + 128 * AP + 128 * BP };

    const int tid  = threadIdx.x;
    const int m0   = blockIdx.x * 128;
    const int rel0 = blockIdx.y * 4;

    const uint32_t a_u32  = smem_u32(a_s);
    const uint32_t w_u32[2] = { smem_u32(w_s[0]), smem_u32(w_s[1]) };

    #pragma unroll
    for (int i = tid; i < 128 * 16; i += 256) {
        int row = i >> 4, c8 = i & 15;
        cp_async16(a_u32 + (row * AP + c8 * 8) * 2,
                   g_h1h + (size_t)(m0 + row) * H_DIM + c8 * 8);
    }
    // pair 0: rels rel0 (cols 0-63), rel0+1 (cols 64-127)
    #pragma unroll
    for (int i = tid; i < 128 * 16; i += 256) {
        int row = i >> 4, c8 = i & 15;
        const __half* Wsrc = g_W2h + (size_t)(rel0 + (c8 >> 3)) * H_DIM * OUT_DIM
                           + (size_t)row * OUT_DIM + (c8 & 7) * 8;
        cp_async16(w_u32[0] + (row * BP + c8 * 8) * 2, Wsrc);
    }
    CP_COMMIT();

    const int wid = tid >> 5;
    const int wm  = wid & 3;
    const int wn  = wid >> 2;     // selects rel within pair

    #pragma unroll
    for (int p = 0; p < 2; p++) {
        CP_WAIT0();
        __syncthreads();

        if (p == 0) {
            #pragma unroll
            for (int i = tid; i < 128 * 16; i += 256) {
                int row = i >> 4, c8 = i & 15;
                const __half* Wsrc = g_W2h + (size_t)(rel0 + 2 + (c8 >> 3)) * H_DIM * OUT_DIM
                                   + (size_t)row * OUT_DIM + (c8 & 7) * 8;
                cp_async16(w_u32[1] + (row * BP + c8 * 8) * 2, Wsrc);
            }
            CP_COMMIT();
        }

        __half* b_s = w_s[p];

        wmma::fragment<wmma::accumulator, 16, 16, 16, float> acc[2][NF];
        #pragma unroll
        for (int i = 0; i < 2; i++)
            #pragma unroll
            for (int j = 0; j < NF; j++)
                wmma::fill_fragment(acc[i][j], 0.f);

        #pragma unroll
        for (int k0 = 0; k0 < 128; k0 += 16) {
            wmma::fragment<wmma::matrix_a, 16, 16, 16, __half, wmma::row_major> af[2];
            #pragma unroll
            for (int i = 0; i < 2; i++)
                wmma::load_matrix_sync(af[i], a_s + (wm * 32 + i * 16) * AP + k0, AP);
            #pragma unroll
            for (int j = 0; j < NF; j++) {
                wmma::fragment<wmma::matrix_b, 16, 16, 16, __half, wmma::row_major> bf;
                wmma::load_matrix_sync(bf, b_s + k0 * BP + wn * 64 + j * 16, BP);
                #pragma unroll
                for (int i = 0; i < 2; i++)
                    wmma::mma_sync(acc[i][j], af[i], bf, acc[i][j]);
            }
        }

        // store: warp wn writes rel (rel0 + 2p + wn), full 64 cols
        __half* Yp = g_Y2h + (size_t)(rel0 + 2 * p + wn) * N_PAD * OUT_DIM;
        #pragma unroll
        for (int i = 0; i < 2; i++)
            #pragma unroll
            for (int j = 0; j < NF; j++) {
                wmma::fragment<wmma::accumulator, 16, 16, 16, __half> hacc;
                #pragma unroll
                for (int e = 0; e < hacc.num_elements; e++)
                    hacc.x[e] = __float2half(acc[i][j].x[e]);
                wmma::store_matrix_sync(
                    Yp + (size_t)(m0 + wm * 32 + i * 16) * OUT_DIM + j * 16,
                    hacc, OUT_DIM, wmma::mem_row_major);
            }
    }
}

// ---------------- edge scatter ----------------
__device__ __forceinline__ void red_add_v4(float* p, float4 v) {
    asm volatile("red.global.add.v4.f32 [%0], {%1, %2, %3, %4};"
                 :: "l"(p), "f"(v.x), "f"(v.y), "f"(v.z), "f"(v.w) : "memory");
}

// layer 1: one warp per edge; packed record, v4 reductions
__global__ void scatter1_kernel() {
    int e = (blockIdx.x * blockDim.x + threadIdx.x) >> 5;
    if (e >= N_EDGES) return;
    int4 rec = __ldg(g_edges + e);
    int   lane = threadIdx.x & 31;
    float nm   = __int_as_float(rec.w);

    uint2 v = __ldg((const uint2*)(g_Y1h + ((size_t)rec.x * N_PAD + rec.y) * H_DIM) + lane);
    float2 f0 = __half22float2(*(__half2*)&v.x);
    float2 f1 = __half22float2(*(__half2*)&v.y);
    red_add_v4(g_h1 + (size_t)rec.z * H_DIM + lane * 4,
               make_float4(f0.x * nm, f0.y * nm, f1.x * nm, f1.y * nm));
}

// layer 2: two edges per warp (16 lanes each); packed record, v4 reductions
__global__ void scatter2_kernel(float* __restrict__ out_ext) {
    int t = blockIdx.x * blockDim.x + threadIdx.x;
    int e = t >> 4;
    if (e >= N_EDGES) return;
    int4 rec = __ldg(g_edges + e);
    int   lane = t & 15;
    float nm   = __int_as_float(rec.w);

    uint2 v = __ldg((const uint2*)(g_Y2h + ((size_t)rec.x * N_PAD + rec.y) * OUT_DIM) + lane);
    float2 f0 = __half22float2(*(__half2*)&v.x);
    float2 f1 = __half22float2(*(__half2*)&v.y);
    red_add_v4(out_ext + (size_t)rec.z * OUT_DIM + lane * 4,
               make_float4(f0.x * nm, f0.y * nm, f1.x * nm, f1.y * nm));
}

// ---------------- epilogues ----------------
__global__ void bias_relu_kernel(const float* __restrict__ bias1) {
    int i = blockIdx.x * blockDim.x + threadIdx.x;
    if (i < N_NODES * 32) {
        int c4 = i & 31;
        float4 v = ((float4*)g_h1)[i];
        const float4 b = ((const float4*)bias1)[c4];
        v.x = fmaxf(v.x + b.x, 0.f);
        v.y = fmaxf(v.y + b.y, 0.f);
        v.z = fmaxf(v.z + b.z, 0.f);
        v.w = fmaxf(v.w + b.w, 0.f);
        ((float4*)g_h1)[i] = v;
        __half2 h0 = __floats2half2_rn(v.x, v.y);
        __half2 h1v = __floats2half2_rn(v.z, v.w);
        ((uint2*)g_h1h)[i] = make_uint2(*(uint32_t*)&h0, *(uint32_t*)&h1v);
    }
}

__global__ void bias2_kernel(const float* __restrict__ bias2,
                             float* __restrict__ out_ext) {
    int i = blockIdx.x * blockDim.x + threadIdx.x;
    if (i < N_NODES * 16) {
        int c4 = i & 15;
        float4 v = ((float4*)out_ext)[i];
        const float4 b = ((const float4*)bias2)[c4];
        v.x += b.x; v.y += b.y; v.z += b.z; v.w += b.w;
        ((float4*)out_ext)[i] = v;
    }
}

// ---------------- launch ----------------
extern "C" void kernel_launch(void* const* d_in, const int* in_sizes, int n_in,
                              void* d_out, int out_size) {
    const int*   node_ids = (const int*)  d_in[0];
    const int*   src      = (const int*)  d_in[1];
    const int*   dst      = (const int*)  d_in[2];
    const int*   etype    = (const int*)  d_in[3];
    const float* norm     = (const float*)d_in[4];
    const float* emb      = (const float*)d_in[5];
    const float* V1       = (const float*)d_in[6];
    const float* comp1    = (const float*)d_in[7];
    const float* bias1    = (const float*)d_in[8];
    const float* V2       = (const float*)d_in[9];
    const float* comp2    = (const float*)d_in[10];
    const float* bias2    = (const float*)d_in[11];
    float*       out      = (float*)d_out;

    const int T = 256;
    const int SMEM1 = (128 * 136 + 2 * 128 * 136) * 2;   // 104448
    const int SMEM2 = (128 * 136 + 2 * 128 * 136) * 2;   // 104448 (paired BN=128)
    cudaFuncSetAttribute(gemm1_wmma_kernel, cudaFuncAttributeMaxDynamicSharedMemorySize, SMEM1);
    cudaFuncSetAttribute(gemm2_wmma_kernel, cudaFuncAttributeMaxDynamicSharedMemorySize, SMEM2);

    // prep: gather X (fp16) + zero h1/out + pack edges
    {
        long long n = (long long)N_NODES * 64 + N_EDGES;
        prep_kernel<<<(unsigned)((n + T - 1) / T), T>>>(node_ids, emb, out,
                                                        etype, src, dst, norm);
    }
    // combine basis weights -> fp16
    {
        dim3 g1((H_DIM * H_DIM + T - 1) / T, N_RELS);
        compute_W_kernel<H_DIM><<<g1, T>>>(comp1, V1);
        dim3 g2((H_DIM * OUT_DIM + T - 1) / T, N_RELS);
        compute_W_kernel<OUT_DIM><<<g2, T>>>(comp2, V2);
    }

    // ---- layer 1 ----
    gemm1_wmma_kernel<<<dim3(N_PAD / 128, N_RELS / 4), 256, SMEM1>>>();
    {
        long long threads = (long long)N_EDGES * 32;
        scatter1_kernel<<<(unsigned)((threads + T - 1) / T), T>>>();
    }
    bias_relu_kernel<<<(N_NODES * 32 + T - 1) / T, T>>>(bias1);

    // ---- layer 2 ----
    gemm2_wmma_kernel<<<dim3(N_PAD / 128, N_RELS / 4), 256, SMEM2>>>();
    {
        long long threads = (long long)N_EDGES * 16;
        scatter2_kernel<<<(unsigned)((threads + T - 1) / T), T>>>(out);
    }
    bias2_kernel<<<(N_NODES * 16 + T - 1) / T, T>>>(bias2, out);
}